// round 8
// baseline (speedup 1.0000x reference)
#include <cuda_runtime.h>
#include <math.h>

#define T_STEPS   32768
#define N_NEUR    1024
#define FILT_LEN  200
#define THREADS   256
#define CHUNK     1024
#define NCH       (T_STEPS / CHUNK)
#define PAD       64

#define LOG_DT_F      (-6.907755278982137f)
#define NOISE_SIGMA_F (0.2f)
#define INH_FACTOR_F  (0.8187307530779818f)
#define INH_INC_F     (3000.0f)

// scratch (no cudaMalloc allowed)
__device__ float          g_thr[T_STEPS];
__device__ unsigned short g_loc[T_STEPS];
__device__ int            g_cnt[NCH * 32];   // padded: one counter per 128B line
__device__ float          g_filt[FILT_LEN];  // FIR taps, precomputed once

__global__ void init_kernel() {
    const int i = threadIdx.x;
    if (i < NCH * 32) g_cnt[i] = 0;
    if (i < FILT_LEN) g_filt[i] = expf(-((float)i) * 0.05f);  // bit-identical to R6 taps
}

// ---------------------------------------------------------------------------
// Fused kernel. Block 0 = persistent scanner (first wave, always co-resident).
// Blocks 1..T_STEPS = one time-step row each (producer). Producers never wait
// on anything -> forward progress guaranteed.
// R7: producers use __expf (MUFU) + table'd FIR taps; scanner keeps the decay
// state W = A*F^k in a register with per-lane F-power constants (no LDS on the
// decision chain).
// ---------------------------------------------------------------------------
__global__ void __launch_bounds__(THREADS)
fused_kernel(const float* __restrict__ inputs,
             const float* __restrict__ noise_rand,
             const float* __restrict__ u_mult,
             const float* __restrict__ rand_val,
             float* __restrict__ out)
{
    const int tid  = threadIdx.x;
    const int lane = tid & 31;
    const unsigned FULL = 0xffffffffu;
    const size_t IDX_INH = (size_t)T_STEPS * N_NEUR;

    __shared__ float          s_fp[PAD + 1];          // F^0..F^64
    __shared__ float          s_thr[2][CHUNK + PAD];  // pad = -inf (never spikes)
    __shared__ unsigned short s_loc[2][CHUNK];
    __shared__ float s_max[8];
    __shared__ float s_ns[8];
    __shared__ float s_wsum[8];
    __shared__ int   s_cnt[8];
    __shared__ float s_b[2];

    if (blockIdx.x != 0) {
        // =================== PRODUCER: row t = blockIdx.x - 1 ===============
        const int t   = blockIdx.x - 1;
        const int wid = tid >> 5;

        const float4 x4 =
            reinterpret_cast<const float4*>(inputs)[(size_t)t * (N_NEUR / 4) + tid];

        // noise tap: noise[t] = sum_j nr[t-j] * filt[j]   (filt from table)
        float prod = 0.0f;
        if (tid < FILT_LEN) {
            int idx = t - tid;
            if (idx >= 0) prod = (noise_rand[idx] * NOISE_SIGMA_F) * g_filt[tid];
        }

        // joint warp reduce: row max + noise sum
        float lm = fmaxf(fmaxf(x4.x, x4.y), fmaxf(x4.z, x4.w));
        #pragma unroll
        for (int o = 16; o; o >>= 1) {
            lm   = fmaxf(lm, __shfl_xor_sync(FULL, lm, o));
            prod += __shfl_xor_sync(FULL, prod, o);
        }
        if (lane == 0) { s_max[wid] = lm; s_ns[wid] = prod; }
        __syncthreads();
        if (tid == 0) {
            float m = s_max[0], c = s_ns[0];
            #pragma unroll
            for (int i = 1; i < 8; i++) { m = fmaxf(m, s_max[i]); c += s_ns[i]; }
            s_b[0] = c;
            s_b[1] = m + c;     // m' for inputs+noise (monotone rounding)
        }
        __syncthreads();
        const float c  = s_b[0];
        const float mp = s_b[1];

        // fast exp (MUFU.EX2 path): args <= 0, errors ~2-4 ulp near the max
        const float e0 = __expf((x4.x + c) - mp);
        const float e1 = __expf((x4.y + c) - mp);
        const float e2 = __expf((x4.z + c) - mp);
        const float e3 = __expf((x4.w + c) - mp);
        const float p0 = e0;
        const float p1 = p0 + e1;
        const float p2 = p1 + e2;
        const float p3 = p2 + e3;

        float incl = p3;
        #pragma unroll
        for (int o = 1; o < 32; o <<= 1) {
            float n = __shfl_up_sync(FULL, incl, o);
            if (lane >= o) incl += n;
        }
        if (lane == 31) s_wsum[wid] = incl;
        __syncthreads();
        float warp_off = 0.0f, stot = 0.0f;
        {
            float acc = 0.0f;
            #pragma unroll
            for (int i = 0; i < 8; i++) {
                if (i == wid) warp_off = acc;
                acc += s_wsum[i];
            }
            stot = acc;
        }
        float excl = __shfl_up_sync(FULL, incl, 1);
        if (lane == 0) excl = 0.0f;
        const float base = warp_off + excl;

        const float us = u_mult[t] * stot;
        int cnt = (int)((base + p0) < us) + (int)((base + p1) < us)
                + (int)((base + p2) < us) + (int)((base + p3) < us);
        #pragma unroll
        for (int o = 16; o; o >>= 1) cnt += __shfl_xor_sync(FULL, cnt, o);
        if (lane == 0) s_cnt[wid] = cnt;
        __syncthreads();
        if (tid == 0) {
            int total = 0;
            #pragma unroll
            for (int i = 0; i < 8; i++) total += s_cnt[i];
            int loc = (total >= N_NEUR) ? 0 : total;
            g_loc[t] = (unsigned short)loc;
            const float logr = logf(rand_val[t]);             // precise (thr path)
            g_thr[t] = ((logf(stot) + mp) + LOG_DT_F) - logr; // precise log
            out[IDX_INH + T_STEPS + t] = c;    // noise output
        }

        // zero-fill the out_spikes row (scanner scatters rare 1.0s later)
        reinterpret_cast<float4*>(out)[(size_t)t * (N_NEUR / 4) + tid] =
            make_float4(0.0f, 0.0f, 0.0f, 0.0f);

        // release: one fence+atomic per block after the CTA barrier
        __syncthreads();
        if (tid == 0) {
            __threadfence();
            atomicAdd(&g_cnt[(t >> 10) << 5], 1);
        }
        return;
    }

    // ======================= SCANNER (block 0) ==============================
    // F^i table (double-accurate, single fp32 rounding), i = 0..64
    for (int i = tid; i <= PAD; i += THREADS)
        s_fp[i] = (float)exp(-0.2 * (double)i);
    // -inf pads: positions beyond the chunk never spike
    for (int i = tid; i < PAD; i += THREADS) {
        s_thr[0][CHUNK + i] = __int_as_float(0xff800000);
        s_thr[1][CHUNK + i] = __int_as_float(0xff800000);
    }
    __syncthreads();

    // stage chunk 0 (all 8 warps); one thread polls
    if (tid == 0) {
        while (*((volatile int*)&g_cnt[0]) < CHUNK) __nanosleep(256);
        __threadfence();   // acquire
    }
    __syncthreads();
    for (int i = tid; i < CHUNK; i += THREADS) {
        s_thr[0][i] = g_thr[i];
        s_loc[0][i] = g_loc[i];
    }
    __syncthreads();

    // per-lane decay constants (registers; off the critical chain after init)
    const int   l2  = lane << 1;
    const float C0  = s_fp[l2];        // F^(2l)
    const float C1  = s_fp[l2 + 1];    // F^(2l+1)
    const float C2  = s_fp[l2 + 2];    // F^(2l+2)

    // Scan state: Wv = w_p (inh value entering step p). v_{p+i} = Wv * F^i.
    float Wv = 0.0f;
    int   p  = 0;

    for (int ch = 0; ch < NCH; ++ch) {
        if (tid >= 32) {
            // warps 1..7: poll (lane 0 only) + stage next chunk
            const int cn = ch + 1;
            if (cn < NCH) {
                if (lane == 0) {
                    while (*((volatile int*)&g_cnt[cn << 5]) < CHUNK)
                        __nanosleep(256);
                    __threadfence();   // acquire
                }
                __syncwarp();
                float*          dt = s_thr[cn & 1];
                unsigned short* dl = s_loc[cn & 1];
                const int off = cn * CHUNK;
                for (int i = tid - 32; i < CHUNK; i += THREADS - 32) {
                    dt[i] = g_thr[off + i];
                    dl[i] = g_loc[off + i];
                }
            }
        } else {
            // warp 0: scan chunk ch from smem (register-resident decay chain)
            const float*          thrb = s_thr[ch & 1];
            const unsigned short* locb = s_loc[ch & 1];
            const int cbase = ch * CHUNK;
            const int cend  = cbase + CHUNK;

            while (p < cend) {
                const int rem = cend - p;                 // >= 1
                const int i0  = (p - cbase) + l2;         // pad makes reads safe

                const float thr0 = thrb[i0];
                const float thr1 = thrb[i0 + 1];

                const float w0 = __fmul_rn(Wv, C0);       // w_{p+l2}
                const float w1 = __fmul_rn(Wv, C1);       // w_{p+l2+1}
                const float w2 = __fmul_rn(Wv, C2);       // w_{p+l2+2}

                const unsigned m0 = __ballot_sync(FULL, w0 < thr0);
                const unsigned m1 = __ballot_sync(FULL, w1 < thr1);

                if (m0 | m1) {
                    const int j0 = m0 ? ((__ffs(m0) - 1) << 1)       : (1 << 30);
                    const int j1 = m1 ? (((__ffs(m1) - 1) << 1) | 1) : (1 << 30);
                    const int j  = min(j0, j1);           // first spike offset (< rem)

                    // lane (j>>1) holds w_{j+1}: w1 if its even slot fired first
                    const float cand = ((m0 >> lane) & 1u) ? w1 : w2;
                    const float wn   = __shfl_sync(FULL, cand, j >> 1);
                    const float An   = __fadd_rn(wn, INH_INC_F);  // serial: w_j*F + 3000

                    if (l2 < j)        out[IDX_INH + (p + l2)]     = w1;
                    else if (l2 == j)  out[IDX_INH + (p + l2)]     = An;
                    if (l2 + 1 < j)    out[IDX_INH + (p + l2 + 1)] = w2;
                    else if (l2 + 1 == j) out[IDX_INH + (p + l2 + 1)] = An;

                    if (lane == (j >> 1)) {
                        const int ts = p + j;
                        out[(size_t)ts * N_NEUR + (int)locb[ts - cbase]] = 1.0f;
                    }
                    Wv = An; p += j + 1;
                } else {
                    if (l2 < rem)      out[IDX_INH + (p + l2)]     = w1;
                    if (l2 + 1 < rem)  out[IDX_INH + (p + l2 + 1)] = w2;
                    const int adv = min(PAD, rem);
                    Wv = __fmul_rn(Wv, s_fp[adv]);        // boundary-only LDS
                    p += adv;
                }
            }
        }
        __syncthreads();
    }
}

extern "C" void kernel_launch(void* const* d_in, const int* in_sizes, int n_in,
                              void* d_out, int out_size)
{
    const float* inputs     = (const float*)d_in[0];
    const float* noise_rand = (const float*)d_in[1];
    const float* u_mult     = (const float*)d_in[2];
    const float* rand_val   = (const float*)d_in[3];
    float* out = (float*)d_out;

    init_kernel<<<1, NCH * 32>>>();
    fused_kernel<<<T_STEPS + 1, THREADS>>>(inputs, noise_rand, u_mult, rand_val, out);
}